// round 5
// baseline (speedup 1.0000x reference)
#include <cuda_runtime.h>
#include <cstdint>

// Problem constants (fixed by the dataset)
#define ENTRY_SIZE 8192
#define TUPLE_SIZE 16
#define N_NEURONS  512
#define ADDR_BITS  16
#define BATCH      4096

#define NPG        4                    // neurons per group (per block)
#define GROUPS     (N_NEURONS / NPG)    // 128
#define TPB        512                  // threads per block = samples per tile
#define HALF       (BATCH / 2)          // main kernel split into 2 launches

// Scratch: normalized mapping + identity flag + per-(group,sample) partials.
__device__ int   g_map[ENTRY_SIZE];
__device__ int   g_identity;
__device__ float g_ps[GROUPS * BATCH];  // 2 MB
__device__ int   g_pc[GROUPS * BATCH];  // 2 MB

// ---------------------------------------------------------------------------
// Load helpers.
//  - Input: 256-bit loads, L2 evict_first (stream-once; protect table residency).
//  - Tables: L2 evict_last via createpolicy (touched sectors ~105MB < L2 126MB,
//    persists across graph replays).
// ---------------------------------------------------------------------------
__device__ __forceinline__ void ld256_stream(const int* p, int v[8]) {
    asm("ld.global.nc.L2::evict_first.v8.b32 {%0,%1,%2,%3,%4,%5,%6,%7}, [%8];"
        : "=r"(v[0]), "=r"(v[1]), "=r"(v[2]), "=r"(v[3]),
          "=r"(v[4]), "=r"(v[5]), "=r"(v[6]), "=r"(v[7])
        : "l"(p));
}
__device__ __forceinline__ unsigned long long mk_policy_last() {
    unsigned long long p;
    asm("createpolicy.fractional.L2::evict_last.b64 %0, 1.0;" : "=l"(p));
    return p;
}
__device__ __forceinline__ int ld_tab_i32(const int* p, unsigned long long pol) {
    int v;
    asm("ld.global.nc.L2::cache_hint.b32 %0, [%1], %2;" : "=r"(v) : "l"(p), "l"(pol));
    return v;
}
__device__ __forceinline__ float ld_tab_f32(const float* p, unsigned long long pol) {
    float v;
    asm("ld.global.nc.L2::cache_hint.f32 %0, [%1], %2;" : "=f"(v) : "l"(p), "l"(pol));
    return v;
}

// ---------------------------------------------------------------------------
// Prep: normalize tuple_mapping (int32 or int64, probe-detected) into g_map,
// set g_identity.
// ---------------------------------------------------------------------------
__global__ void prep_kernel(const void* __restrict__ map_raw) {
    __shared__ int flag;
    if (threadIdx.x == 0) flag = 1;
    __syncthreads();

    const long long* m64 = (const long long*)map_raw;
    const int*       m32 = (const int*)map_raw;
    long long probe = m64[1];
    bool is64 = (probe >= 0 && probe < (long long)ENTRY_SIZE);

    bool ok = true;
    for (int i = threadIdx.x; i < ENTRY_SIZE; i += blockDim.x) {
        int v = is64 ? (int)m64[i] : m32[i];
        g_map[i] = v;
        if (v != i) ok = false;
    }
    if (!ok) atomicExch(&flag, 0);
    __syncthreads();
    if (threadIdx.x == 0) g_identity = flag;
}

// ---------------------------------------------------------------------------
// Main: block = (neuron group g, sample tile). Thread = one sample, NPG
// neurons. Neuron-major scheduling keeps each group's table sectors hot in
// L2 (evict_last); input slice [g*64, g*64+64) ints is exclusive to group g
// and read with full 128B-line utilization.
// ---------------------------------------------------------------------------
__global__ __launch_bounds__(TPB, 2)
void wisard_main(const int*   __restrict__ input,
                 const int*   __restrict__ counts,
                 const float* __restrict__ sums,
                 int sample_base) {
    const int g = blockIdx.x & (GROUPS - 1);
    const int tile = blockIdx.x >> 7;           // GROUPS = 128 = 2^7
    const int b = sample_base + tile * TPB + threadIdx.x;

    const unsigned long long pol_last = mk_policy_last();
    const bool ident = (g_identity != 0);

    unsigned addr[NPG];
    if (ident) {
        const int* row = input + (size_t)b * ENTRY_SIZE + g * (NPG * TUPLE_SIZE);
#pragma unroll
        for (int j = 0; j < NPG; j++) {
            int lo[8], hi[8];
            ld256_stream(row + j * TUPLE_SIZE,     lo);
            ld256_stream(row + j * TUPLE_SIZE + 8, hi);
            unsigned a = 0;
#pragma unroll
            for (int i = 0; i < 8; i++) a |= (unsigned)(lo[i] & 1) << (15 - i);
#pragma unroll
            for (int i = 0; i < 8; i++) a |= (unsigned)(hi[i] & 1) << (7 - i);
            addr[j] = a;
        }
    } else {
        const int* base = input + (size_t)b * ENTRY_SIZE;
#pragma unroll
        for (int j = 0; j < NPG; j++) {
            const int n = g * NPG + j;
            unsigned a = 0;
#pragma unroll
            for (int t = 0; t < TUPLE_SIZE; t++) {
                int bit = base[g_map[n * TUPLE_SIZE + t]] & 1;
                a |= (unsigned)bit << (TUPLE_SIZE - 1 - t);
            }
            addr[j] = a;
        }
    }

    // Counts gathers back-to-back (MLP=4), then predicated sums gathers.
    int c[NPG];
#pragma unroll
    for (int j = 0; j < NPG; j++) {
        const size_t idx = ((size_t)(g * NPG + j) << ADDR_BITS) | addr[j];
        c[j] = ld_tab_i32(counts + idx, pol_last);
    }

    float rs = 0.0f;
    int   rc = 0;
#pragma unroll
    for (int j = 0; j < NPG; j++) {
        const size_t idx = ((size_t)(g * NPG + j) << ADDR_BITS) | addr[j];
        if (c[j] > 0) {
            rs += ld_tab_f32(sums + idx, pol_last);
            rc += c[j];
        }
    }

    // Coalesced partial store (lanes = consecutive samples).
    g_ps[g * BATCH + b] = rs;
    g_pc[g * BATCH + b] = rc;
}

// ---------------------------------------------------------------------------
// Final: thread = sample; reduce 128 group partials (coalesced), divide.
// ---------------------------------------------------------------------------
__global__ __launch_bounds__(TPB)
void wisard_final(float* __restrict__ out) {
    const int b = blockIdx.x * TPB + threadIdx.x;
    float rs = 0.0f;
    int   rc = 0;
#pragma unroll 4
    for (int g = 0; g < GROUPS; g++) {
        rs += g_ps[g * BATCH + b];
        rc += g_pc[g * BATCH + b];
    }
    // counters == 0 implies response == 0 too -> nan_to_num(0/0) = 0
    out[b] = (rc > 0) ? (rs / (float)rc) : 0.0f;
}

extern "C" void kernel_launch(void* const* d_in, const int* in_sizes, int n_in,
                              void* d_out, int out_size) {
    const int*   input   = (const int*)d_in[0];
    const void*  mapping = d_in[1];              // int32 or int64 (detected)
    const int*   counts  = (const int*)d_in[2];
    const float* sums    = (const float*)d_in[3];
    float*       out     = (float*)d_out;

    // 4 launches/call so ncu (-s 5 -c 1) lands on wisard_main.
    prep_kernel<<<1, TPB>>>(mapping);
    wisard_main<<<GROUPS * (HALF / TPB), TPB>>>(input, counts, sums, 0);
    wisard_main<<<GROUPS * (HALF / TPB), TPB>>>(input, counts, sums, HALF);
    wisard_final<<<BATCH / TPB, TPB>>>(out);
}

// round 6
// speedup vs baseline: 1.3404x; 1.3404x over previous
#include <cuda_runtime.h>
#include <cstdint>

// Problem constants (fixed by the dataset)
#define ENTRY_SIZE 8192
#define TUPLE_SIZE 16
#define N_NEURONS  512
#define ADDR_BITS  16
#define BATCH      4096

#define NPG        4                    // neurons per group (per block)
#define GROUPS     (N_NEURONS / NPG)    // 128
#define TPB        512                  // threads per block = samples per tile
#define TILES      (BATCH / TPB)        // 8 tiles per group
#define GHALF      (GROUPS / 2)         // main split by group into 2 launches

// Scratch: normalized mapping + identity flag + per-(group,sample) partials.
__device__ int   g_map[ENTRY_SIZE];
__device__ int   g_identity;
__device__ float g_ps[GROUPS * BATCH];  // 2 MB
__device__ int   g_pc[GROUPS * BATCH];  // 2 MB

// ---------------------------------------------------------------------------
// Load helpers.
//  - Input: 256-bit loads, L2 evict_first (stream-once; protect table residency).
//  - Tables: L2 evict_last via createpolicy.
// ---------------------------------------------------------------------------
__device__ __forceinline__ void ld256_stream(const int* p, int v[8]) {
    asm("ld.global.nc.L2::evict_first.v8.b32 {%0,%1,%2,%3,%4,%5,%6,%7}, [%8];"
        : "=r"(v[0]), "=r"(v[1]), "=r"(v[2]), "=r"(v[3]),
          "=r"(v[4]), "=r"(v[5]), "=r"(v[6]), "=r"(v[7])
        : "l"(p));
}
__device__ __forceinline__ unsigned long long mk_policy_last() {
    unsigned long long p;
    asm("createpolicy.fractional.L2::evict_last.b64 %0, 1.0;" : "=l"(p));
    return p;
}
__device__ __forceinline__ int ld_tab_i32(const int* p, unsigned long long pol) {
    int v;
    asm("ld.global.nc.L2::cache_hint.b32 %0, [%1], %2;" : "=r"(v) : "l"(p), "l"(pol));
    return v;
}
__device__ __forceinline__ float ld_tab_f32(const float* p, unsigned long long pol) {
    float v;
    asm("ld.global.nc.L2::cache_hint.f32 %0, [%1], %2;" : "=f"(v) : "l"(p), "l"(pol));
    return v;
}

// ---------------------------------------------------------------------------
// Prep: normalize tuple_mapping (int32 or int64, probe-detected) into g_map,
// set g_identity.
// ---------------------------------------------------------------------------
__global__ void prep_kernel(const void* __restrict__ map_raw) {
    __shared__ int flag;
    if (threadIdx.x == 0) flag = 1;
    __syncthreads();

    const long long* m64 = (const long long*)map_raw;
    const int*       m32 = (const int*)map_raw;
    long long probe = m64[1];
    bool is64 = (probe >= 0 && probe < (long long)ENTRY_SIZE);

    bool ok = true;
    for (int i = threadIdx.x; i < ENTRY_SIZE; i += blockDim.x) {
        int v = is64 ? (int)m64[i] : m32[i];
        g_map[i] = v;
        if (v != i) ok = false;
    }
    if (!ok) atomicExch(&flag, 0);
    __syncthreads();
    if (threadIdx.x == 0) g_identity = flag;
}

// ---------------------------------------------------------------------------
// Main: block = (group g, sample tile), GROUP-CONTIGUOUS blockIdx so the
// ~296 concurrently-resident CTAs span only ~37 groups -> concurrent table
// working set ~67MB < L2. Each touched 128B table line is then fetched once
// and reused ~2.3x within the group's pass over the batch.
// Thread = one sample, NPG neurons.
// ---------------------------------------------------------------------------
__global__ __launch_bounds__(TPB, 2)
void wisard_main(const int*   __restrict__ input,
                 const int*   __restrict__ counts,
                 const float* __restrict__ sums,
                 int group_base) {
    const int g    = group_base + (blockIdx.x >> 3);   // TILES = 8
    const int tile = blockIdx.x & (TILES - 1);
    const int b    = tile * TPB + threadIdx.x;

    const unsigned long long pol_last = mk_policy_last();
    const bool ident = (g_identity != 0);

    unsigned addr[NPG];
    if (ident) {
        const int* row = input + (size_t)b * ENTRY_SIZE + g * (NPG * TUPLE_SIZE);
#pragma unroll
        for (int j = 0; j < NPG; j++) {
            int lo[8], hi[8];
            ld256_stream(row + j * TUPLE_SIZE,     lo);
            ld256_stream(row + j * TUPLE_SIZE + 8, hi);
            unsigned a = 0;
#pragma unroll
            for (int i = 0; i < 8; i++) a |= (unsigned)(lo[i] & 1) << (15 - i);
#pragma unroll
            for (int i = 0; i < 8; i++) a |= (unsigned)(hi[i] & 1) << (7 - i);
            addr[j] = a;
        }
    } else {
        const int* base = input + (size_t)b * ENTRY_SIZE;
#pragma unroll
        for (int j = 0; j < NPG; j++) {
            const int n = g * NPG + j;
            unsigned a = 0;
#pragma unroll
            for (int t = 0; t < TUPLE_SIZE; t++) {
                int bit = base[g_map[n * TUPLE_SIZE + t]] & 1;
                a |= (unsigned)bit << (TUPLE_SIZE - 1 - t);
            }
            addr[j] = a;
        }
    }

    // Counts gathers back-to-back (MLP=4), then predicated sums gathers.
    int c[NPG];
#pragma unroll
    for (int j = 0; j < NPG; j++) {
        const size_t idx = ((size_t)(g * NPG + j) << ADDR_BITS) | addr[j];
        c[j] = ld_tab_i32(counts + idx, pol_last);
    }

    float rs = 0.0f;
    int   rc = 0;
#pragma unroll
    for (int j = 0; j < NPG; j++) {
        const size_t idx = ((size_t)(g * NPG + j) << ADDR_BITS) | addr[j];
        if (c[j] > 0) {
            rs += ld_tab_f32(sums + idx, pol_last);
            rc += c[j];
        }
    }

    // Coalesced partial store (lanes = consecutive samples).
    g_ps[g * BATCH + b] = rs;
    g_pc[g * BATCH + b] = rc;
}

// ---------------------------------------------------------------------------
// Final: 64 blocks x 512 threads. Each block finishes 64 samples; each
// sample's 128 group-partials are reduced by 8 threads (16 groups each),
// coalesced loads, then a small smem reduction.
// ---------------------------------------------------------------------------
__global__ __launch_bounds__(TPB)
void wisard_final(float* __restrict__ out) {
    const int bl = threadIdx.x & 63;        // sample within block
    const int k  = threadIdx.x >> 6;        // 0..7 reduction slice
    const int b  = blockIdx.x * 64 + bl;

    float rs = 0.0f;
    int   rc = 0;
#pragma unroll
    for (int i = 0; i < 16; i++) {
        const int g = k * 16 + i;
        rs += g_ps[g * BATCH + b];
        rc += g_pc[g * BATCH + b];
    }

    __shared__ float s_s[8][64];
    __shared__ int   s_c[8][64];
    s_s[k][bl] = rs;
    s_c[k][bl] = rc;
    __syncthreads();

    if (k == 0) {
        float r  = 0.0f;
        int   c2 = 0;
#pragma unroll
        for (int i = 0; i < 8; i++) { r += s_s[i][bl]; c2 += s_c[i][bl]; }
        // counters == 0 implies response == 0 too -> nan_to_num(0/0) = 0
        out[b] = (c2 > 0) ? (r / (float)c2) : 0.0f;
    }
}

extern "C" void kernel_launch(void* const* d_in, const int* in_sizes, int n_in,
                              void* d_out, int out_size) {
    const int*   input   = (const int*)d_in[0];
    const void*  mapping = d_in[1];              // int32 or int64 (detected)
    const int*   counts  = (const int*)d_in[2];
    const float* sums    = (const float*)d_in[3];
    float*       out     = (float*)d_out;

    // 4 launches/call: ncu (-s 5 -c 1) lands on the first wisard_main of call 2.
    prep_kernel<<<1, TPB>>>(mapping);
    wisard_main<<<GHALF * TILES, TPB>>>(input, counts, sums, 0);
    wisard_main<<<GHALF * TILES, TPB>>>(input, counts, sums, GHALF);
    wisard_final<<<BATCH / 64, TPB>>>(out);
}